// round 1
// baseline (speedup 1.0000x reference)
#include <cuda_runtime.h>
#include <cuda_bf16.h>
#include <math.h>

#define N_NODES 65536
#define EMBED 512
#define FFDIM 2048
#define NHEADS 8
#define HDIM 64

// -------------------- scratch (static device globals; no runtime alloc) -----
__device__ float g_h[(size_t)N_NODES * EMBED];     // LN output (reused for LN1, LN2)
__device__ float g_q[(size_t)N_NODES * EMBED];
__device__ float g_k[(size_t)N_NODES * EMBED];
__device__ float g_v[(size_t)N_NODES * EMBED];
__device__ float g_attn[(size_t)N_NODES * EMBED];  // attention output
__device__ float g_x1[(size_t)N_NODES * EMBED];    // residual after attn block
__device__ float g_ffh[(size_t)N_NODES * FFDIM];   // FF hidden

// -------------------- LayerNorm: one block (128 thr) per row of 512 ---------
__global__ void __launch_bounds__(128) ln_kernel(
    const float* __restrict__ x, const float* __restrict__ gamma,
    const float* __restrict__ beta, float* __restrict__ y)
{
    int row = blockIdx.x;
    int t = threadIdx.x;             // 0..127, each handles 4 floats
    const float4* xp = (const float4*)(x + (size_t)row * EMBED);
    float4 v = xp[t];
    float s  = v.x + v.y + v.z + v.w;
    float s2 = v.x*v.x + v.y*v.y + v.z*v.z + v.w*v.w;

    // warp reduce
    #pragma unroll
    for (int off = 16; off > 0; off >>= 1) {
        s  += __shfl_down_sync(0xffffffffu, s,  off);
        s2 += __shfl_down_sync(0xffffffffu, s2, off);
    }
    __shared__ float red[2][4];
    int warp = t >> 5, lane = t & 31;
    if (lane == 0) { red[0][warp] = s; red[1][warp] = s2; }
    __syncthreads();
    float tot  = red[0][0] + red[0][1] + red[0][2] + red[0][3];
    float tot2 = red[1][0] + red[1][1] + red[1][2] + red[1][3];
    float mu  = tot  * (1.0f / EMBED);
    float var = tot2 * (1.0f / EMBED) - mu * mu;
    float inv = rsqrtf(var + 1e-5f);

    float4 g4 = ((const float4*)gamma)[t];
    float4 b4 = ((const float4*)beta)[t];
    float4 o;
    o.x = (v.x - mu) * inv * g4.x + b4.x;
    o.y = (v.y - mu) * inv * g4.y + b4.y;
    o.z = (v.z - mu) * inv * g4.z + b4.z;
    o.w = (v.w - mu) * inv * g4.w + b4.w;
    ((float4*)(y + (size_t)row * EMBED))[t] = o;
}

// -------------------- generic SGEMM: C[N,M] = A[N,K] @ B[M,K]^T + epilogue --
// B row-major [M,K] (K contiguous) == the W.T pattern of the reference.
// 128x128 block tile, BK=16, 256 threads, 8x8 microtile.
#define GBM 128
#define GBN 128
#define GBK 16

__global__ void __launch_bounds__(256) gemm_kernel(
    const float* __restrict__ A, const float* __restrict__ B,
    const float* __restrict__ bias, const float* __restrict__ res,
    float* __restrict__ C, int N, int M, int K, int relu)
{
    __shared__ float As[GBK][GBM + 4];
    __shared__ float Bs[GBK][GBN + 4];

    int bm = blockIdx.y * GBM;
    int bn = blockIdx.x * GBN;
    int tid = threadIdx.x;
    int tx = tid & 15;   // col group (0..15)
    int ty = tid >> 4;   // row group (0..15)

    float acc[8][8];
    #pragma unroll
    for (int i = 0; i < 8; i++)
        #pragma unroll
        for (int j = 0; j < 8; j++) acc[i][j] = 0.0f;

    for (int k0 = 0; k0 < K; k0 += GBK) {
        // load A tile (128x16) and B tile (128x16), transposed into [k][mn]
        #pragma unroll
        for (int ld = 0; ld < 2; ld++) {
            int id = tid + ld * 256;         // 0..511
            int r  = id >> 2;                // 0..127
            int kq = (id & 3) * 4;           // 0,4,8,12
            float4 a = *(const float4*)&A[(size_t)(bm + r) * K + k0 + kq];
            As[kq + 0][r] = a.x; As[kq + 1][r] = a.y;
            As[kq + 2][r] = a.z; As[kq + 3][r] = a.w;
            float4 b = *(const float4*)&B[(size_t)(bn + r) * K + k0 + kq];
            Bs[kq + 0][r] = b.x; Bs[kq + 1][r] = b.y;
            Bs[kq + 2][r] = b.z; Bs[kq + 3][r] = b.w;
        }
        __syncthreads();

        #pragma unroll
        for (int kk = 0; kk < GBK; kk++) {
            float ra[8], rb[8];
            #pragma unroll
            for (int i = 0; i < 8; i++) ra[i] = As[kk][ty * 8 + i];
            #pragma unroll
            for (int j = 0; j < 8; j++) rb[j] = Bs[kk][tx * 8 + j];
            #pragma unroll
            for (int i = 0; i < 8; i++)
                #pragma unroll
                for (int j = 0; j < 8; j++)
                    acc[i][j] = fmaf(ra[i], rb[j], acc[i][j]);
        }
        __syncthreads();
    }

    // epilogue: bias (+relu) (+residual)
    #pragma unroll
    for (int i = 0; i < 8; i++) {
        int row = bm + ty * 8 + i;
        float* crow = C + (size_t)row * M;
        const float* rrow = res ? (res + (size_t)row * M) : nullptr;
        #pragma unroll
        for (int j = 0; j < 8; j++) {
            int col = bn + tx * 8 + j;
            float c = acc[i][j] + bias[col];
            if (relu) c = fmaxf(c, 0.0f);
            if (rrow) c += rrow[col];
            crow[col] = c;
        }
    }
}

// -------------------- per-node attention over heads (8x8 scores) ------------
// 256 threads/block = 4 nodes, 64 threads per node.
__global__ void __launch_bounds__(256) attn_kernel(
    const float* __restrict__ q, const float* __restrict__ k,
    const float* __restrict__ v, float* __restrict__ out)
{
    int slot = threadIdx.x >> 6;           // 0..3
    int t    = threadIdx.x & 63;           // 0..63
    int node = blockIdx.x * 4 + slot;

    __shared__ float sq[4][EMBED];
    __shared__ float sk[4][EMBED];
    __shared__ float sv[4][EMBED];
    __shared__ float ss[4][64];

    const float* qp = q + (size_t)node * EMBED;
    const float* kp = k + (size_t)node * EMBED;
    const float* vp = v + (size_t)node * EMBED;
    #pragma unroll
    for (int i = t; i < EMBED; i += 64) {
        sq[slot][i] = qp[i];
        sk[slot][i] = kp[i];
        sv[slot][i] = vp[i];
    }
    __syncthreads();

    // scores: thread t -> pair (h = t/8, g = t%8)
    int h = t >> 3, g = t & 7;
    float s = 0.0f;
    #pragma unroll
    for (int d = 0; d < HDIM; d++)
        s = fmaf(sq[slot][h * HDIM + d], sk[slot][g * HDIM + d], s);
    ss[slot][t] = s * 0.125f;   // 1/sqrt(64)
    __syncthreads();

    // softmax over g for each row h (threads t<8 each do one row)
    if (t < 8) {
        float m = -1e30f;
        #pragma unroll
        for (int gg = 0; gg < 8; gg++) m = fmaxf(m, ss[slot][t * 8 + gg]);
        float sum = 0.0f;
        #pragma unroll
        for (int gg = 0; gg < 8; gg++) {
            float e = expf(ss[slot][t * 8 + gg] - m);
            ss[slot][t * 8 + gg] = e;
            sum += e;
        }
        float invs = 1.0f / sum;
        #pragma unroll
        for (int gg = 0; gg < 8; gg++) ss[slot][t * 8 + gg] *= invs;
    }
    __syncthreads();

    // out[h*64+d] = sum_g attn[h][g] * v[g*64+d]; thread t covers d=t, h=j
    float* op = out + (size_t)node * EMBED;
    #pragma unroll
    for (int j = 0; j < NHEADS; j++) {
        float o = 0.0f;
        #pragma unroll
        for (int gg = 0; gg < 8; gg++)
            o = fmaf(ss[slot][j * 8 + gg], sv[slot][gg * HDIM + t], o);
        op[j * HDIM + t] = o;
    }
}

// -------------------- host orchestration ------------------------------------
extern "C" void kernel_launch(void* const* d_in, const int* in_sizes, int n_in,
                              void* d_out, int out_size)
{
    const float* x    = (const float*)d_in[0];
    const float* Wq   = (const float*)d_in[1];
    const float* bq   = (const float*)d_in[2];
    const float* Wk   = (const float*)d_in[3];
    const float* bk   = (const float*)d_in[4];
    const float* Wv   = (const float*)d_in[5];
    const float* bv   = (const float*)d_in[6];
    const float* Wo   = (const float*)d_in[7];
    const float* bo   = (const float*)d_in[8];
    const float* W1   = (const float*)d_in[9];
    const float* b1   = (const float*)d_in[10];
    const float* W2   = (const float*)d_in[11];
    const float* b2   = (const float*)d_in[12];
    const float* g1   = (const float*)d_in[13];
    const float* be1  = (const float*)d_in[14];
    const float* g2   = (const float*)d_in[15];
    const float* be2  = (const float*)d_in[16];
    float* out = (float*)d_out;

    float *h, *q, *k, *v, *attn, *x1, *ffh;
    cudaGetSymbolAddress((void**)&h,    g_h);
    cudaGetSymbolAddress((void**)&q,    g_q);
    cudaGetSymbolAddress((void**)&k,    g_k);
    cudaGetSymbolAddress((void**)&v,    g_v);
    cudaGetSymbolAddress((void**)&attn, g_attn);
    cudaGetSymbolAddress((void**)&x1,   g_x1);
    cudaGetSymbolAddress((void**)&ffh,  g_ffh);

    // 1) h = LN1(x)
    ln_kernel<<<N_NODES, 128>>>(x, g1, be1, h);

    // 2) q/k/v = h @ W{q,k,v}^T + b
    dim3 blk(256);
    dim3 grdE(EMBED / GBN, N_NODES / GBM);   // (4, 512)
    gemm_kernel<<<grdE, blk>>>(h, Wq, bq, nullptr, q, N_NODES, EMBED, EMBED, 0);
    gemm_kernel<<<grdE, blk>>>(h, Wk, bk, nullptr, k, N_NODES, EMBED, EMBED, 0);
    gemm_kernel<<<grdE, blk>>>(h, Wv, bv, nullptr, v, N_NODES, EMBED, EMBED, 0);

    // 3) per-node attention
    attn_kernel<<<N_NODES / 4, 256>>>(q, k, v, attn);

    // 4) x1 = x + attn @ Wo^T + bo
    gemm_kernel<<<grdE, blk>>>(attn, Wo, bo, x, x1, N_NODES, EMBED, EMBED, 0);

    // 5) h = LN2(x1)
    ln_kernel<<<N_NODES, 128>>>(x1, g2, be2, h);

    // 6) ffh = relu(h @ W1^T + b1)
    dim3 grdF(FFDIM / GBN, N_NODES / GBM);   // (16, 512)
    gemm_kernel<<<grdF, blk>>>(h, W1, b1, nullptr, ffh, N_NODES, FFDIM, EMBED, 1);

    // 7) out = x1 + ffh @ W2^T + b2
    gemm_kernel<<<grdE, blk>>>(ffh, W2, b2, x1, out, N_NODES, EMBED, FFDIM, 0);
}

// round 3
// speedup vs baseline: 5.1646x; 5.1646x over previous
#include <cuda_runtime.h>
#include <cuda_fp16.h>
#include <math.h>
#include <stdint.h>

#define N_NODES 65536
#define EMBED 512
#define FFDIM 2048
#define NHEADS 8
#define HDIM 64

// ---------------- scratch ----------------------------------------------------
__device__ __half g_h[(size_t)N_NODES * EMBED];       // LN output (fp16)
__device__ float  g_q[(size_t)N_NODES * EMBED];
__device__ float  g_k[(size_t)N_NODES * EMBED];
__device__ float  g_v[(size_t)N_NODES * EMBED];
__device__ __half g_attnh[(size_t)N_NODES * EMBED];   // attention out (fp16)
__device__ float  g_x1[(size_t)N_NODES * EMBED];
__device__ __half g_ffh[(size_t)N_NODES * FFDIM];     // FF hidden (fp16)
// fp16 weights
__device__ __half g_wq[EMBED * EMBED];
__device__ __half g_wk[EMBED * EMBED];
__device__ __half g_wv[EMBED * EMBED];
__device__ __half g_wo[EMBED * EMBED];
__device__ __half g_w1[FFDIM * EMBED];
__device__ __half g_w2[EMBED * FFDIM];

// ---------------- ptx helpers ------------------------------------------------
__device__ __forceinline__ uint32_t smem_u32(const void* p) {
    uint32_t a;
    asm("{ .reg .u64 t; cvta.to.shared.u64 t, %1; cvt.u32.u64 %0, t; }" : "=r"(a) : "l"(p));
    return a;
}
__device__ __forceinline__ void cp_async16(uint32_t saddr, const void* gaddr) {
    asm volatile("cp.async.cg.shared.global [%0], [%1], 16;\n" :: "r"(saddr), "l"(gaddr));
}
__device__ __forceinline__ void ldm_x4(uint32_t* r, uint32_t addr) {
    asm volatile("ldmatrix.sync.aligned.m8n8.x4.shared.b16 {%0,%1,%2,%3}, [%4];"
                 : "=r"(r[0]), "=r"(r[1]), "=r"(r[2]), "=r"(r[3]) : "r"(addr));
}
__device__ __forceinline__ void mma16816(float* d, const uint32_t* a, const uint32_t* b) {
    asm volatile(
        "mma.sync.aligned.m16n8k16.row.col.f32.f16.f16.f32 "
        "{%0,%1,%2,%3}, {%4,%5,%6,%7}, {%8,%9}, {%0,%1,%2,%3};"
        : "+f"(d[0]), "+f"(d[1]), "+f"(d[2]), "+f"(d[3])
        : "r"(a[0]), "r"(a[1]), "r"(a[2]), "r"(a[3]), "r"(b[0]), "r"(b[1]));
}

// ---------------- HMMA fp16 GEMM: C[N,M] = A[N,K] @ B[M,K]^T + epilogue -----
// CTA tile 128x128, BK=32. 8 warps (4x2), warp tile 32x64.
// SMEM row stride 80B => bank-group (5r+c)&7 bijective over 8 rows:
// conflict-free ldmatrix without XOR swizzle.
#define BM 128
#define BN 128
#define BK 32
#define ROWB 80                    // bytes per SMEM row (32 halfs + 16B pad)
#define TILEB (128 * ROWB)         // 10240 per tile

template<bool RELU, bool HASRES, bool OUTHALF>
__global__ void __launch_bounds__(256) gemm16_kernel(
    const __half* __restrict__ A, const __half* __restrict__ B,
    const float* __restrict__ bias, const float* __restrict__ res,
    void* __restrict__ Cv, int K, int M)
{
    __shared__ __align__(16) char smem[4 * TILEB];   // A0 B0 A1 B1
    const uint32_t sb = smem_u32(smem);
    const int tid = threadIdx.x;
    const int lane = tid & 31;
    const int wid = tid >> 5;
    const int wm = wid & 3;          // warp row group (32 rows each)
    const int wn = wid >> 2;         // warp col group (64 cols each)
    const int bm = blockIdx.y * BM;
    const int bn = blockIdx.x * BN;

    // global load slots: 2 segs for A, 2 for B per thread
    const int r0 = tid >> 2, c0 = tid & 3;               // seg tid
    const int r1 = (tid + 256) >> 2, c1 = tid & 3;       // seg tid+256
    const __half* agp0 = A + (size_t)(bm + r0) * K + c0 * 8;
    const __half* agp1 = A + (size_t)(bm + r1) * K + c1 * 8;
    const __half* bgp0 = B + (size_t)(bn + r0) * K + c0 * 8;
    const __half* bgp1 = B + (size_t)(bn + r1) * K + c1 * 8;
    const uint32_t so0 = r0 * ROWB + c0 * 16;
    const uint32_t so1 = r1 * ROWB + c1 * 16;

    // ldmatrix per-lane offsets
    uint32_t a_off[2], b_off[4];
#pragma unroll
    for (int mf = 0; mf < 2; mf++)
        a_off[mf] = (wm * 32 + mf * 16 + (lane & 15)) * ROWB + ((lane >> 4) * 16);
#pragma unroll
    for (int p = 0; p < 4; p++)
        b_off[p] = (wn * 64 + p * 16 + ((lane >> 4) << 3) + (lane & 7)) * ROWB
                 + (((lane >> 3) & 1) * 16);

    float acc[2][8][4];
#pragma unroll
    for (int i = 0; i < 2; i++)
#pragma unroll
        for (int j = 0; j < 8; j++)
#pragma unroll
            for (int t = 0; t < 4; t++) acc[i][j][t] = 0.f;

    const int NC = K >> 5;

    // prefetch chunk 0 into buffer 0
    {
        const uint32_t ab = sb, bb = sb + TILEB;
        cp_async16(ab + so0, agp0); cp_async16(ab + so1, agp1);
        cp_async16(bb + so0, bgp0); cp_async16(bb + so1, bgp1);
        asm volatile("cp.async.commit_group;\n");
    }

    for (int chunk = 0; chunk < NC; chunk++) {
        if (chunk + 1 < NC) {
            const uint32_t base = sb + ((chunk + 1) & 1) * (2 * TILEB);
            const int ko = (chunk + 1) * BK;
            cp_async16(base + so0, agp0 + ko); cp_async16(base + TILEB + so1, bgp1 + ko);
            cp_async16(base + so1, agp1 + ko); cp_async16(base + TILEB + so0, bgp0 + ko);
            asm volatile("cp.async.commit_group;\n");
            asm volatile("cp.async.wait_group 1;\n" ::: "memory");
        } else {
            asm volatile("cp.async.wait_group 0;\n" ::: "memory");
        }
        __syncthreads();

        const uint32_t ab = sb + (chunk & 1) * (2 * TILEB);
        const uint32_t bb = ab + TILEB;
#pragma unroll
        for (int ks = 0; ks < 2; ks++) {
            uint32_t afr[2][4], bfr[4][4];
            ldm_x4(afr[0], ab + a_off[0] + ks * 32);
            ldm_x4(afr[1], ab + a_off[1] + ks * 32);
#pragma unroll
            for (int p = 0; p < 4; p++) ldm_x4(bfr[p], bb + b_off[p] + ks * 32);
#pragma unroll
            for (int mf = 0; mf < 2; mf++)
#pragma unroll
                for (int nf = 0; nf < 8; nf++)
                    mma16816(acc[mf][nf], afr[mf], &bfr[nf >> 1][(nf & 1) * 2]);
        }
        __syncthreads();
    }

    // epilogue
    const int mrow = bm + wm * 32 + (lane >> 2);
    const int ncol = bn + wn * 64 + (lane & 3) * 2;
#pragma unroll
    for (int mf = 0; mf < 2; mf++) {
#pragma unroll
        for (int half8 = 0; half8 < 2; half8++) {
            const int row = mrow + mf * 16 + half8 * 8;
#pragma unroll
            for (int nf = 0; nf < 8; nf++) {
                const int col = ncol + nf * 8;
                float c0 = acc[mf][nf][half8 * 2 + 0];
                float c1 = acc[mf][nf][half8 * 2 + 1];
                float2 b2 = *(const float2*)&bias[col];
                c0 += b2.x; c1 += b2.y;
                if (RELU) { c0 = fmaxf(c0, 0.f); c1 = fmaxf(c1, 0.f); }
                if (HASRES) {
                    float2 r2 = *(const float2*)&res[(size_t)row * M + col];
                    c0 += r2.x; c1 += r2.y;
                }
                if (OUTHALF) {
                    *(__half2*)((__half*)Cv + (size_t)row * M + col) =
                        __floats2half2_rn(c0, c1);
                } else {
                    *(float2*)((float*)Cv + (size_t)row * M + col) =
                        make_float2(c0, c1);
                }
            }
        }
    }
}

// ---------------- LayerNorm -> fp16 ------------------------------------------
__global__ void __launch_bounds__(128) ln_kernel(
    const float* __restrict__ x, const float* __restrict__ gamma,
    const float* __restrict__ beta, __half* __restrict__ y)
{
    int row = blockIdx.x;
    int t = threadIdx.x;
    const float4* xp = (const float4*)(x + (size_t)row * EMBED);
    float4 v = xp[t];
    float s  = v.x + v.y + v.z + v.w;
    float s2 = v.x*v.x + v.y*v.y + v.z*v.z + v.w*v.w;
#pragma unroll
    for (int off = 16; off > 0; off >>= 1) {
        s  += __shfl_down_sync(0xffffffffu, s,  off);
        s2 += __shfl_down_sync(0xffffffffu, s2, off);
    }
    __shared__ float red[2][4];
    int warp = t >> 5, lane = t & 31;
    if (lane == 0) { red[0][warp] = s; red[1][warp] = s2; }
    __syncthreads();
    float tot  = red[0][0] + red[0][1] + red[0][2] + red[0][3];
    float tot2 = red[1][0] + red[1][1] + red[1][2] + red[1][3];
    float mu  = tot  * (1.0f / EMBED);
    float var = tot2 * (1.0f / EMBED) - mu * mu;
    float inv = rsqrtf(var + 1e-5f);
    float4 g4 = ((const float4*)gamma)[t];
    float4 b4 = ((const float4*)beta)[t];
    __half2* yp = (__half2*)(y + (size_t)row * EMBED) + t * 2;
    yp[0] = __floats2half2_rn((v.x - mu) * inv * g4.x + b4.x,
                              (v.y - mu) * inv * g4.y + b4.y);
    yp[1] = __floats2half2_rn((v.z - mu) * inv * g4.z + b4.z,
                              (v.w - mu) * inv * g4.w + b4.w);
}

// ---------------- per-node attention (8x8 heads) -> fp16 ---------------------
__global__ void __launch_bounds__(256) attn_kernel(
    const float* __restrict__ q, const float* __restrict__ k,
    const float* __restrict__ v, __half* __restrict__ out)
{
    int slot = threadIdx.x >> 6;
    int t    = threadIdx.x & 63;
    int node = blockIdx.x * 4 + slot;

    __shared__ float sq[4][EMBED];
    __shared__ float sk[4][EMBED];
    __shared__ float sv[4][EMBED];
    __shared__ float ss[4][64];

    const float* qp = q + (size_t)node * EMBED;
    const float* kp = k + (size_t)node * EMBED;
    const float* vp = v + (size_t)node * EMBED;
#pragma unroll
    for (int i = t; i < EMBED; i += 64) {
        sq[slot][i] = qp[i]; sk[slot][i] = kp[i]; sv[slot][i] = vp[i];
    }
    __syncthreads();

    int h = t >> 3, g = t & 7;
    float s = 0.0f;
#pragma unroll
    for (int d = 0; d < HDIM; d++)
        s = fmaf(sq[slot][h * HDIM + d], sk[slot][g * HDIM + d], s);
    ss[slot][t] = s * 0.125f;
    __syncthreads();

    if (t < 8) {
        float m = -1e30f;
#pragma unroll
        for (int gg = 0; gg < 8; gg++) m = fmaxf(m, ss[slot][t * 8 + gg]);
        float sum = 0.0f;
#pragma unroll
        for (int gg = 0; gg < 8; gg++) {
            float e = expf(ss[slot][t * 8 + gg] - m);
            ss[slot][t * 8 + gg] = e;
            sum += e;
        }
        float invs = 1.0f / sum;
#pragma unroll
        for (int gg = 0; gg < 8; gg++) ss[slot][t * 8 + gg] *= invs;
    }
    __syncthreads();

    __half* op = out + (size_t)node * EMBED;
#pragma unroll
    for (int j = 0; j < NHEADS; j++) {
        float o = 0.0f;
#pragma unroll
        for (int gg = 0; gg < 8; gg++)
            o = fmaf(ss[slot][j * 8 + gg], sv[slot][gg * HDIM + t], o);
        op[j * HDIM + t] = __float2half(o);
    }
}

// ---------------- weight fp32 -> fp16 ----------------------------------------
__global__ void __launch_bounds__(256) f2h_kernel(
    const float* __restrict__ s, __half* __restrict__ d)
{
    int i = blockIdx.x * blockDim.x + threadIdx.x;
    float4 v = ((const float4*)s)[i];
    __half2* dp = (__half2*)d + i * 2;
    dp[0] = __floats2half2_rn(v.x, v.y);
    dp[1] = __floats2half2_rn(v.z, v.w);
}

// ---------------- host orchestration -----------------------------------------
extern "C" void kernel_launch(void* const* d_in, const int* in_sizes, int n_in,
                              void* d_out, int out_size)
{
    const float* x   = (const float*)d_in[0];
    const float* Wq  = (const float*)d_in[1];
    const float* bq  = (const float*)d_in[2];
    const float* Wk  = (const float*)d_in[3];
    const float* bk  = (const float*)d_in[4];
    const float* Wv  = (const float*)d_in[5];
    const float* bv  = (const float*)d_in[6];
    const float* Wo  = (const float*)d_in[7];
    const float* bo  = (const float*)d_in[8];
    const float* W1  = (const float*)d_in[9];
    const float* b1  = (const float*)d_in[10];
    const float* W2  = (const float*)d_in[11];
    const float* b2  = (const float*)d_in[12];
    const float* g1  = (const float*)d_in[13];
    const float* be1 = (const float*)d_in[14];
    const float* g2  = (const float*)d_in[15];
    const float* be2 = (const float*)d_in[16];
    float* out = (float*)d_out;

    __half *h, *attnh, *ffh, *wq, *wk, *wv, *wo, *w1, *w2;
    float *q, *k, *v, *x1;
    cudaGetSymbolAddress((void**)&h,     g_h);
    cudaGetSymbolAddress((void**)&q,     g_q);
    cudaGetSymbolAddress((void**)&k,     g_k);
    cudaGetSymbolAddress((void**)&v,     g_v);
    cudaGetSymbolAddress((void**)&attnh, g_attnh);
    cudaGetSymbolAddress((void**)&x1,    g_x1);
    cudaGetSymbolAddress((void**)&ffh,   g_ffh);
    cudaGetSymbolAddress((void**)&wq,    g_wq);
    cudaGetSymbolAddress((void**)&wk,    g_wk);
    cudaGetSymbolAddress((void**)&wv,    g_wv);
    cudaGetSymbolAddress((void**)&wo,    g_wo);
    cudaGetSymbolAddress((void**)&w1,    g_w1);
    cudaGetSymbolAddress((void**)&w2,    g_w2);

    // weight conversions
    f2h_kernel<<<(EMBED*EMBED)/4/256, 256>>>(Wq, wq);
    f2h_kernel<<<(EMBED*EMBED)/4/256, 256>>>(Wk, wk);
    f2h_kernel<<<(EMBED*EMBED)/4/256, 256>>>(Wv, wv);
    f2h_kernel<<<(EMBED*EMBED)/4/256, 256>>>(Wo, wo);
    f2h_kernel<<<(FFDIM*EMBED)/4/256, 256>>>(W1, w1);
    f2h_kernel<<<(EMBED*FFDIM)/4/256, 256>>>(W2, w2);

    // 1) h = LN1(x) -> fp16
    ln_kernel<<<N_NODES, 128>>>(x, g1, be1, h);

    // 2) q/k/v = h @ W^T + b (fp32 out)
    dim3 grdE(EMBED / BN, N_NODES / BM);   // (4, 512)
    gemm16_kernel<false,false,false><<<grdE, 256>>>(h, wq, bq, nullptr, q, EMBED, EMBED);
    gemm16_kernel<false,false,false><<<grdE, 256>>>(h, wk, bk, nullptr, k, EMBED, EMBED);
    gemm16_kernel<false,false,false><<<grdE, 256>>>(h, wv, bv, nullptr, v, EMBED, EMBED);

    // 3) per-node attention -> fp16
    attn_kernel<<<N_NODES / 4, 256>>>(q, k, v, attnh);

    // 4) x1 = x + attnh @ Wo^T + bo (fp32)
    gemm16_kernel<false,true,false><<<grdE, 256>>>(attnh, wo, bo, x, x1, EMBED, EMBED);

    // 5) h = LN2(x1) -> fp16
    ln_kernel<<<N_NODES, 128>>>(x1, g2, be2, h);

    // 6) ffh = relu(h @ W1^T + b1) -> fp16
    dim3 grdF(FFDIM / BN, N_NODES / BM);   // (16, 512)
    gemm16_kernel<true,false,true><<<grdF, 256>>>(h, w1, b1, nullptr, ffh, EMBED, FFDIM);

    // 7) out = x1 + ffh @ W2^T + b2 (fp32)
    gemm16_kernel<false,true,false><<<grdE, 256>>>(ffh, w2, b2, x1, out, FFDIM, EMBED);
}